// round 4
// baseline (speedup 1.0000x reference)
#include <cuda_runtime.h>
#include <math.h>

// Problem constants
#define PB 16      // batch
#define PS 4096    // sequence
#define PD 64      // head dim
#define PH 8       // n_hashes
#define PNB 64     // n_buckets
#define PCHUNKS 512 // chunks per batch (PH * PNB), each of 64 tokens

// ---------------- scratch (device globals; no allocation allowed) ----------
__device__ unsigned char g_bucket[PB * PH * PS];            // 512 KB
__device__ int           g_st[PB * PH * PS];                // 2 MB   sorted pos -> original t
__device__ float         g_lse[PB * PH * PS];               // 2 MB   [b][h][t]
__device__ float         g_o[(size_t)PB * PH * PS * PD];    // 128 MB [b][h][t][d]

// ---------------------------------------------------------------------------
// Kernel 1: hashing. rotated[i] = sum_f qk[b,t,f] * rot[f,h,i]; argmax over
// [rotated, -rotated] with first-occurrence tie-breaking (match jnp.argmax).
// grid: PB*(PS/256) blocks, 256 threads. Each thread owns one token.
// ---------------------------------------------------------------------------
__global__ void __launch_bounds__(256) k_hash(
    const float* __restrict__ qk, const float* __restrict__ rot,
    float* __restrict__ out_tail, int write_buckets)
{
    __shared__ float rot_s[64 * 32];   // rotations for one hash round: [f][i]
    int b = blockIdx.x >> 4;
    int t = ((blockIdx.x & 15) << 8) + threadIdx.x;

    const float* qr = qk + ((size_t)b * PS + t) * PD;
    float q[64];
#pragma unroll
    for (int f4 = 0; f4 < 16; f4++) {
        float4 v4 = ((const float4*)qr)[f4];
        q[f4 * 4 + 0] = v4.x; q[f4 * 4 + 1] = v4.y;
        q[f4 * 4 + 2] = v4.z; q[f4 * 4 + 3] = v4.w;
    }

    for (int h = 0; h < PH; h++) {
        __syncthreads();
        for (int e = threadIdx.x; e < 2048; e += 256) {
            int f = e >> 5, i = e & 31;
            rot_s[e] = rot[f * 256 + h * 32 + i];  // rot layout [f][h][i] (b bcast)
        }
        __syncthreads();

        float bestp = -1e30f, bestn = -1e30f;
        int ip = 0, inn = 0;
        for (int i0 = 0; i0 < 32; i0 += 4) {
            float a0 = 0.f, a1 = 0.f, a2 = 0.f, a3 = 0.f;
#pragma unroll
            for (int f = 0; f < 64; f++) {
                float4 rr = *(const float4*)&rot_s[f * 32 + i0];  // broadcast LDS.128
                a0 += q[f] * rr.x; a1 += q[f] * rr.y;
                a2 += q[f] * rr.z; a3 += q[f] * rr.w;
            }
            if ( a0 > bestp) { bestp =  a0; ip  = i0 + 0; }
            if (-a0 > bestn) { bestn = -a0; inn = i0 + 0; }
            if ( a1 > bestp) { bestp =  a1; ip  = i0 + 1; }
            if (-a1 > bestn) { bestn = -a1; inn = i0 + 1; }
            if ( a2 > bestp) { bestp =  a2; ip  = i0 + 2; }
            if (-a2 > bestn) { bestn = -a2; inn = i0 + 2; }
            if ( a3 > bestp) { bestp =  a3; ip  = i0 + 3; }
            if (-a3 > bestn) { bestn = -a3; inn = i0 + 3; }
        }
        int idx = (bestp >= bestn) ? ip : (32 + inn);  // plus-half wins ties (first occurrence)
        g_bucket[((size_t)b * PH + h) * PS + t] = (unsigned char)idx;
        if (write_buckets)
            out_tail[((size_t)b * PH + h) * PS + t] = (float)(idx + h * PNB);
    }
}

// ---------------------------------------------------------------------------
// Kernel 2: stable counting sort per (b,h): 4096 tokens into 64 buckets by
// (bucket, t) — exactly jnp.argsort of S*bucket + t. grid: PB*PH, 128 threads.
// ---------------------------------------------------------------------------
__global__ void __launch_bounds__(128) k_sort()
{
    __shared__ unsigned char sb[4096];
    __shared__ int hist[64];
    __shared__ int offs[64];
    int bh = blockIdx.x;
    int tid = threadIdx.x;

    if (tid < 64) hist[tid] = 0;
    const unsigned int* src = (const unsigned int*)(g_bucket + (size_t)bh * PS);
    unsigned int* dstb = (unsigned int*)sb;
    for (int i = tid; i < 1024; i += 128) dstb[i] = src[i];
    __syncthreads();

    for (int t = tid; t < 4096; t += 128) atomicAdd(&hist[sb[t]], 1);
    __syncthreads();

    if (tid == 0) {
        int run = 0;
        for (int k = 0; k < 64; k++) { offs[k] = run; run += hist[k]; }
    }
    __syncthreads();

    if (tid < 64) {
        int k = tid;
        int pos = offs[k];
        int* dst = g_st + (size_t)bh * PS;
        for (int t = 0; t < 4096; t++)
            if (sb[t] == (unsigned char)k) dst[pos++] = t;  // stable: t ascending
    }
}

// ---------------------------------------------------------------------------
// Kernel 3: chunk attention. One CTA per (b, chunk c in [0,512)).
//   Q = qk rows of chunk (64x64), K = normalized rows of chunk + prev chunk
//   (128x64, wrap over the 512-chunk axis of the batch, crossing hash rounds).
//   dots = Q K^T * D^-0.5; self-mask (orig position equal) -> -1e5; softmax;
//   O = P V. Results scattered by st (fused unsort).
// 256 threads, dynamic smem 83200 B.
// ---------------------------------------------------------------------------
#define SM_Q   (64 * 65)     // 4160 floats
#define SM_KV  (64 * 129)    // 8256 floats (K^T pad 129; reused for V [128][64])
#define SM_DOT (64 * 129)    // 8256 floats
#define SMEM3_BYTES ((SM_Q + SM_KV + SM_DOT) * 4 + 128 * 4)

__global__ void __launch_bounds__(256) k_attn(
    const float* __restrict__ qk, const float* __restrict__ v)
{
    extern __shared__ float sm[];
    float* q_s  = sm;                     // [i*65 + f]
    float* kv_s = sm + SM_Q;              // K^T: [f*129 + j]; later V: [j*64 + d]
    float* dots = sm + SM_Q + SM_KV;      // [i*129 + j]
    int*   st_k = (int*)(dots + SM_DOT);  // 128 orig positions (0..63 = Q chunk)

    int tid = threadIdx.x;
    int b = blockIdx.x >> 9;
    int c = blockIdx.x & 511;
    int h  = c >> 6;
    int cp = (c + 511) & 511;
    int hp = cp >> 6;

    if (tid < 64) {
        st_k[tid]      = g_st[((size_t)b * PH + h ) * PS + (c  & 63) * 64 + tid];
        st_k[64 + tid] = g_st[((size_t)b * PH + hp) * PS + (cp & 63) * 64 + tid];
    }
    __syncthreads();

    // ---- load Q (raw) ----
    {
        int i  = tid >> 2;
        int f0 = (tid & 3) * 16;
        const float* row = qk + ((size_t)b * PS + st_k[i]) * PD + f0;
#pragma unroll
        for (int u = 0; u < 4; u++) {
            float4 v4 = ((const float4*)row)[u];
            int f = f0 + u * 4;
            q_s[i * 65 + f + 0] = v4.x; q_s[i * 65 + f + 1] = v4.y;
            q_s[i * 65 + f + 2] = v4.z; q_s[i * 65 + f + 3] = v4.w;
        }
    }
    // ---- load K: row-normalized (clip 1e-12), transposed ----
    if (tid < 128) {
        int j = tid;
        const float* row = qk + ((size_t)b * PS + st_k[j]) * PD;
        float r[64];
        float ss = 0.f;
#pragma unroll
        for (int u = 0; u < 16; u++) {
            float4 v4 = ((const float4*)row)[u];
            r[u * 4 + 0] = v4.x; r[u * 4 + 1] = v4.y;
            r[u * 4 + 2] = v4.z; r[u * 4 + 3] = v4.w;
            ss += v4.x * v4.x + v4.y * v4.y + v4.z * v4.z + v4.w * v4.w;
        }
        float nrm = fmaxf(sqrtf(ss), 1e-12f);
        float inv = 1.0f / nrm;
#pragma unroll
        for (int f = 0; f < 64; f++) kv_s[f * 129 + j] = r[f] * inv;
    }
    __syncthreads();

    // ---- dots = Q K^T * 0.125 + self-mask ----
    int ty = tid >> 4, tx = tid & 15;   // i = ty + 16*ii, j = tx + 16*jj
    {
        float acc[4][8];
#pragma unroll
        for (int ii = 0; ii < 4; ii++)
#pragma unroll
            for (int jj = 0; jj < 8; jj++) acc[ii][jj] = 0.f;

        for (int kk = 0; kk < 64; kk++) {
            float qr[4], kr[8];
#pragma unroll
            for (int ii = 0; ii < 4; ii++) qr[ii] = q_s[(ty + ii * 16) * 65 + kk];
#pragma unroll
            for (int jj = 0; jj < 8; jj++) kr[jj] = kv_s[kk * 129 + tx + jj * 16];
#pragma unroll
            for (int ii = 0; ii < 4; ii++)
#pragma unroll
                for (int jj = 0; jj < 8; jj++) acc[ii][jj] += qr[ii] * kr[jj];
        }
#pragma unroll
        for (int ii = 0; ii < 4; ii++) {
            int i = ty + ii * 16;
            int ti = st_k[i];
#pragma unroll
            for (int jj = 0; jj < 8; jj++) {
                int j = tx + jj * 16;
                float d = acc[ii][jj] * 0.125f;
                if (ti == st_k[j]) d = -1e5f;   // self-attention mask
                dots[i * 129 + j] = d;
            }
        }
    }
    __syncthreads();

    // ---- load V into kv_s (K^T no longer needed) ----
    {
        int j  = tid >> 1;
        int d0 = (tid & 1) * 32;
        const float* row = v + ((size_t)b * PS + st_k[j]) * PD + d0;
        float* dv = kv_s + j * 64 + d0;
#pragma unroll
        for (int u = 0; u < 8; u++)
            ((float4*)dv)[u] = ((const float4*)row)[u];
    }
    // ---- softmax rows + lse scatter ----
    if (tid < 64) {
        int i = tid;
        float m = -1e30f;
        for (int j = 0; j < 128; j++) m = fmaxf(m, dots[i * 129 + j]);
        float s = 0.f;
        for (int j = 0; j < 128; j++) {
            float e = expf(dots[i * 129 + j] - m);
            dots[i * 129 + j] = e;
            s += e;
        }
        float inv = 1.0f / s;
        for (int j = 0; j < 128; j++) dots[i * 129 + j] *= inv;
        g_lse[((size_t)b * PH + h) * PS + st_k[i]] = m + logf(s);
    }
    __syncthreads();

    // ---- O = P V, scatter by st ----
    {
        float acc[4][4];
#pragma unroll
        for (int ii = 0; ii < 4; ii++)
#pragma unroll
            for (int dd = 0; dd < 4; dd++) acc[ii][dd] = 0.f;

        for (int j = 0; j < 128; j++) {
            float pr[4], vr[4];
#pragma unroll
            for (int ii = 0; ii < 4; ii++) pr[ii] = dots[(ty + ii * 16) * 129 + j];
#pragma unroll
            for (int dd = 0; dd < 4; dd++) vr[dd] = kv_s[j * 64 + tx + dd * 16];
#pragma unroll
            for (int ii = 0; ii < 4; ii++)
#pragma unroll
                for (int dd = 0; dd < 4; dd++) acc[ii][dd] += pr[ii] * vr[dd];
        }
#pragma unroll
        for (int ii = 0; ii < 4; ii++) {
            int i = ty + ii * 16;
            size_t base = (((size_t)b * PH + h) * PS + st_k[i]) * (size_t)PD;
#pragma unroll
            for (int dd = 0; dd < 4; dd++)
                g_o[base + tx + dd * 16] = acc[ii][dd];
        }
    }
}

// ---------------------------------------------------------------------------
// Kernel 4: combine hash rounds: w_h = exp(lse_h - logsumexp_h), out = sum w_h o_h.
// grid: PB*(PS/32), 256 threads. 8-lane groups reduce over hashes via shuffles.
// ---------------------------------------------------------------------------
__global__ void __launch_bounds__(256) k_combine(float* __restrict__ out)
{
    __shared__ float sw[32 * 8];
    int b  = blockIdx.x >> 7;
    int t0 = (blockIdx.x & 127) * 32;
    int tid = threadIdx.x;
    int tl = tid >> 3, h = tid & 7;
    int t = t0 + tl;

    float l = g_lse[((size_t)b * PH + h) * PS + t];
    float m = l;
#pragma unroll
    for (int o = 4; o; o >>= 1) m = fmaxf(m, __shfl_xor_sync(0xffffffffu, m, o));
    float s = expf(l - m);
#pragma unroll
    for (int o = 4; o; o >>= 1) s += __shfl_xor_sync(0xffffffffu, s, o);
    sw[tl * 8 + h] = expf(l - (m + logf(s)));
    __syncthreads();

#pragma unroll
    for (int r = 0; r < 8; r++) {
        int idx = tid + r * 256;
        int tl2 = idx >> 6, d = idx & 63;
        int t2 = t0 + tl2;
        float acc = 0.f;
#pragma unroll
        for (int hh = 0; hh < 8; hh++)
            acc += g_o[(((size_t)b * PH + hh) * PS + t2) * (size_t)PD + d] * sw[tl2 * 8 + hh];
        out[((size_t)b * PS + t2) * (size_t)PD + d] = acc;
    }
}

// ---------------------------------------------------------------------------
extern "C" void kernel_launch(void* const* d_in, const int* in_sizes, int n_in,
                              void* d_out, int out_size)
{
    (void)n_in; (void)in_sizes;
    const float* qk  = (const float*)d_in[0];
    const float* v   = (const float*)d_in[1];
    const float* rot = (const float*)d_in[2];
    float* out = (float*)d_out;

    const int n_main = PB * PS * PD;            // 4194304
    const int n_buck = PB * PH * PS;            // 524288
    int write_buckets = (out_size >= n_main + n_buck) ? 1 : 0;

    cudaFuncSetAttribute(k_attn, cudaFuncAttributeMaxDynamicSharedMemorySize,
                         SMEM3_BYTES);

    k_hash<<<PB * (PS / 256), 256>>>(qk, rot, out + n_main, write_buckets);
    k_sort<<<PB * PH, 128>>>();
    k_attn<<<PB * PCHUNKS, 256, SMEM3_BYTES>>>(qk, v);
    k_combine<<<PB * (PS / 32), 256>>>(out);
}

// round 5
// speedup vs baseline: 1.1335x; 1.1335x over previous
#include <cuda_runtime.h>
#include <math.h>

// Problem constants
#define PB 16      // batch
#define PS 4096    // sequence
#define PD 64      // head dim
#define PH 8       // n_hashes
#define PNB 64     // n_buckets
#define PCHUNKS 512 // chunks per batch (PH * PNB), each of 64 tokens

typedef unsigned long long u64;

// ---- packed fp32x2 helpers (Blackwell FFMA2 path) -------------------------
__device__ __forceinline__ u64 pack2(float x, float y) {
    u64 r; asm("mov.b64 %0, {%1, %2};" : "=l"(r) : "f"(x), "f"(y)); return r;
}
__device__ __forceinline__ float2 unpack2(u64 p) {
    float2 v; asm("mov.b64 {%0, %1}, %2;" : "=f"(v.x), "=f"(v.y) : "l"(p)); return v;
}
__device__ __forceinline__ u64 ffma2(u64 a, u64 b, u64 c) {
    asm("fma.rn.f32x2 %0, %1, %2, %0;" : "+l"(c) : "l"(a), "l"(b));
    return c;
}

// ---------------- scratch (device globals; no allocation allowed) ----------
__device__ unsigned char g_bucket[PB * PH * PS];            // 512 KB
__device__ int           g_st[PB * PH * PS];                // 2 MB   sorted pos -> original t
__device__ float         g_lse[PB * PH * PS];               // 2 MB   [b][h][t]
__device__ float         g_o[(size_t)PB * PH * PS * PD];    // 128 MB [b][h][t][d]

// ---------------------------------------------------------------------------
// Kernel 1: hashing. rotated[i] = sum_f qk[b,t,f] * rot[f,h,i]; argmax over
// [rotated, -rotated] with first-occurrence tie-breaking (match jnp.argmax).
// Packed FFMA2 over bucket pairs: 16 packed accumulators cover 32 buckets.
// grid: PB*(PS/256) blocks, 256 threads. Each thread owns one token.
// ---------------------------------------------------------------------------
__global__ void __launch_bounds__(256) k_hash(
    const float* __restrict__ qk, const float* __restrict__ rot,
    float* __restrict__ out_tail, int write_buckets)
{
    __shared__ float rot_s[64 * 32];   // rotations for one hash round: [f][i]
    int b = blockIdx.x >> 4;
    int t = ((blockIdx.x & 15) << 8) + threadIdx.x;

    const float* qr = qk + ((size_t)b * PS + t) * PD;
    float q[64];
#pragma unroll
    for (int f4 = 0; f4 < 16; f4++) {
        float4 v4 = ((const float4*)qr)[f4];
        q[f4 * 4 + 0] = v4.x; q[f4 * 4 + 1] = v4.y;
        q[f4 * 4 + 2] = v4.z; q[f4 * 4 + 3] = v4.w;
    }

    for (int h = 0; h < PH; h++) {
        __syncthreads();
        for (int e = threadIdx.x; e < 2048; e += 256) {
            int f = e >> 5, i = e & 31;
            rot_s[e] = rot[f * 256 + h * 32 + i];  // rot layout [f][h][i] (b bcast)
        }
        __syncthreads();

        u64 acc[16];
#pragma unroll
        for (int p = 0; p < 16; p++) acc[p] = 0ull;   // (0.0f, 0.0f)

        for (int f = 0; f < 64; f++) {
            u64 qb = pack2(q[f], q[f]);
            const ulonglong2* rr = (const ulonglong2*)&rot_s[f * 32]; // LDS.128 bcast
#pragma unroll
            for (int p2 = 0; p2 < 8; p2++) {
                ulonglong2 vv = rr[p2];
                acc[2 * p2 + 0] = ffma2(qb, vv.x, acc[2 * p2 + 0]);
                acc[2 * p2 + 1] = ffma2(qb, vv.y, acc[2 * p2 + 1]);
            }
        }

        float bestp = -1e30f, bestn = -1e30f;
        int ip = 0, inn = 0;
#pragma unroll
        for (int p = 0; p < 16; p++) {
            float2 a = unpack2(acc[p]);
            int i0 = 2 * p, i1 = 2 * p + 1;
            if ( a.x > bestp) { bestp =  a.x; ip  = i0; }
            if (-a.x > bestn) { bestn = -a.x; inn = i0; }
            if ( a.y > bestp) { bestp =  a.y; ip  = i1; }
            if (-a.y > bestn) { bestn = -a.y; inn = i1; }
        }
        int idx = (bestp >= bestn) ? ip : (32 + inn);  // plus-half wins ties
        g_bucket[((size_t)b * PH + h) * PS + t] = (unsigned char)idx;
        if (write_buckets)
            out_tail[((size_t)b * PH + h) * PS + t] = (float)(idx + h * PNB);
    }
}

// ---------------------------------------------------------------------------
// Kernel 2: stable counting sort per (b,h): 4096 tokens into 64 buckets by
// (bucket, t) — exactly jnp.argsort of S*bucket + t. grid: PB*PH, 128 threads.
// ---------------------------------------------------------------------------
__global__ void __launch_bounds__(128) k_sort()
{
    __shared__ unsigned char sb[4096];
    __shared__ int hist[64];
    __shared__ int offs[64];
    int bh = blockIdx.x;
    int tid = threadIdx.x;

    if (tid < 64) hist[tid] = 0;
    const unsigned int* src = (const unsigned int*)(g_bucket + (size_t)bh * PS);
    unsigned int* dstb = (unsigned int*)sb;
    for (int i = tid; i < 1024; i += 128) dstb[i] = src[i];
    __syncthreads();

    for (int t = tid; t < 4096; t += 128) atomicAdd(&hist[sb[t]], 1);
    __syncthreads();

    if (tid == 0) {
        int run = 0;
        for (int k = 0; k < 64; k++) { offs[k] = run; run += hist[k]; }
    }
    __syncthreads();

    if (tid < 64) {
        int k = tid;
        int pos = offs[k];
        int* dst = g_st + (size_t)bh * PS;
        for (int t = 0; t < 4096; t++)
            if (sb[t] == (unsigned char)k) dst[pos++] = t;  // stable: t ascending
    }
}

// ---------------------------------------------------------------------------
// Kernel 3: chunk attention with packed FFMA2. One CTA per (b, chunk c).
//   Q (64x64 raw), K (128x64 row-normalized, transposed, stride 130),
//   dots = Q K^T * D^-0.5 (self-mask -1e5), softmax (256-thread parallel),
//   O = P V, scatter by st (fused unsort).
// Thread map: ty=tid>>4 (i = ty+16*ii), tx=tid&15 (j/d pairs at 2*tx+32*g).
// 256 threads, dynamic smem 83712 B.
// ---------------------------------------------------------------------------
#define SM_Q   (64 * 65)     // 4160 floats
#define SM_KV  (64 * 130)    // 8320 floats (K^T pad 130; reused for V [128][64])
#define SM_DOT (64 * 130)    // 8320 floats
#define SMEM3_BYTES ((SM_Q + SM_KV + SM_DOT) * 4 + 128 * 4)

__global__ void __launch_bounds__(256) k_attn(
    const float* __restrict__ qk, const float* __restrict__ v)
{
    extern __shared__ float sm[];
    float* q_s  = sm;                     // [i*65 + f]
    float* kv_s = sm + SM_Q;              // K^T: [f*130 + j]; later V: [j*64 + d]
    float* dots = sm + SM_Q + SM_KV;      // [i*130 + j]
    int*   st_k = (int*)(dots + SM_DOT);  // 128 orig positions (0..63 = Q chunk)

    int tid = threadIdx.x;
    int b = blockIdx.x >> 9;
    int c = blockIdx.x & 511;
    int h  = c >> 6;
    int cp = (c + 511) & 511;
    int hp = cp >> 6;

    if (tid < 64) {
        st_k[tid]      = g_st[((size_t)b * PH + h ) * PS + (c  & 63) * 64 + tid];
        st_k[64 + tid] = g_st[((size_t)b * PH + hp) * PS + (cp & 63) * 64 + tid];
    }
    __syncthreads();

    // ---- load Q (raw) ----
    {
        int i  = tid >> 2;
        int f0 = (tid & 3) * 16;
        const float* row = qk + ((size_t)b * PS + st_k[i]) * PD + f0;
#pragma unroll
        for (int u = 0; u < 4; u++) {
            float4 v4 = ((const float4*)row)[u];
            int f = f0 + u * 4;
            q_s[i * 65 + f + 0] = v4.x; q_s[i * 65 + f + 1] = v4.y;
            q_s[i * 65 + f + 2] = v4.z; q_s[i * 65 + f + 3] = v4.w;
        }
    }
    // ---- load K: row-normalized (clip 1e-12), transposed, stride 130 ----
    if (tid < 128) {
        int j = tid;
        const float* row = qk + ((size_t)b * PS + st_k[j]) * PD;
        float r[64];
        float ss = 0.f;
#pragma unroll
        for (int u = 0; u < 16; u++) {
            float4 v4 = ((const float4*)row)[u];
            r[u * 4 + 0] = v4.x; r[u * 4 + 1] = v4.y;
            r[u * 4 + 2] = v4.z; r[u * 4 + 3] = v4.w;
            ss += v4.x * v4.x + v4.y * v4.y + v4.z * v4.z + v4.w * v4.w;
        }
        float nrm = fmaxf(sqrtf(ss), 1e-12f);
        float inv = 1.0f / nrm;
#pragma unroll
        for (int f = 0; f < 64; f++) kv_s[f * 130 + j] = r[f] * inv;
    }
    __syncthreads();

    int ty = tid >> 4, tx = tid & 15;

    // ---- dots = Q K^T * 0.125 + self-mask (FFMA2, packed over j pairs) ----
    {
        u64 acc[4][4];
#pragma unroll
        for (int ii = 0; ii < 4; ii++)
#pragma unroll
            for (int g = 0; g < 4; g++) acc[ii][g] = 0ull;

        for (int kk = 0; kk < 64; kk++) {
            u64 qb[4], kp[4];
#pragma unroll
            for (int ii = 0; ii < 4; ii++) {
                float qv = q_s[(ty + ii * 16) * 65 + kk];
                qb[ii] = pack2(qv, qv);
            }
#pragma unroll
            for (int g = 0; g < 4; g++)
                kp[g] = *(const u64*)&kv_s[kk * 130 + 2 * tx + 32 * g]; // LDS.64
#pragma unroll
            for (int ii = 0; ii < 4; ii++)
#pragma unroll
                for (int g = 0; g < 4; g++)
                    acc[ii][g] = ffma2(qb[ii], kp[g], acc[ii][g]);
        }
#pragma unroll
        for (int ii = 0; ii < 4; ii++) {
            int i = ty + ii * 16;
            int ti = st_k[i];
#pragma unroll
            for (int g = 0; g < 4; g++) {
                int j0 = 2 * tx + 32 * g;
                float2 a = unpack2(acc[ii][g]);
                a.x *= 0.125f; a.y *= 0.125f;
                if (ti == st_k[j0])     a.x = -1e5f;   // self-attention mask
                if (ti == st_k[j0 + 1]) a.y = -1e5f;
                *(float2*)&dots[i * 130 + j0] = a;
            }
        }
    }
    __syncthreads();

    // ---- load V into kv_s (K^T no longer needed) ----
    {
        int j  = tid >> 1;
        int d0 = (tid & 1) * 32;
        const float* row = v + ((size_t)b * PS + st_k[j]) * PD + d0;
        float* dv = kv_s + j * 64 + d0;
#pragma unroll
        for (int u = 0; u < 8; u++)
            ((float4*)dv)[u] = ((const float4*)row)[u];
    }
    // ---- softmax: all 256 threads, 4 threads per row, shfl reductions ----
    {
        int i2 = tid >> 2, q4 = tid & 3;
        float* row = dots + i2 * 130 + q4 * 32;
        float m = -1e30f;
#pragma unroll
        for (int u = 0; u < 16; u++) {
            float2 p = ((const float2*)row)[u];
            m = fmaxf(m, fmaxf(p.x, p.y));
        }
        m = fmaxf(m, __shfl_xor_sync(0xffffffffu, m, 1));
        m = fmaxf(m, __shfl_xor_sync(0xffffffffu, m, 2));
        float s = 0.f;
#pragma unroll
        for (int u = 0; u < 16; u++) {
            float2 p = ((const float2*)row)[u];
            p.x = __expf(p.x - m); p.y = __expf(p.y - m);
            s += p.x + p.y;
            ((float2*)row)[u] = p;
        }
        s += __shfl_xor_sync(0xffffffffu, s, 1);
        s += __shfl_xor_sync(0xffffffffu, s, 2);
        float inv = 1.0f / s;
#pragma unroll
        for (int u = 0; u < 16; u++) {
            float2 p = ((const float2*)row)[u];
            p.x *= inv; p.y *= inv;
            ((float2*)row)[u] = p;
        }
        if (q4 == 0)
            g_lse[((size_t)b * PH + h) * PS + st_k[i2]] = m + __logf(s);
    }
    __syncthreads();

    // ---- O = P V (FFMA2, packed over d pairs), scatter by st ----
    {
        u64 acc[4][2];
#pragma unroll
        for (int ii = 0; ii < 4; ii++) { acc[ii][0] = 0ull; acc[ii][1] = 0ull; }

        for (int j = 0; j < 128; j++) {
            u64 pb[4], vp[2];
#pragma unroll
            for (int ii = 0; ii < 4; ii++) {
                float pv = dots[(ty + ii * 16) * 130 + j];
                pb[ii] = pack2(pv, pv);
            }
#pragma unroll
            for (int g = 0; g < 2; g++)
                vp[g] = *(const u64*)&kv_s[j * 64 + 2 * tx + 32 * g]; // LDS.64
#pragma unroll
            for (int ii = 0; ii < 4; ii++) {
                acc[ii][0] = ffma2(pb[ii], vp[0], acc[ii][0]);
                acc[ii][1] = ffma2(pb[ii], vp[1], acc[ii][1]);
            }
        }
#pragma unroll
        for (int ii = 0; ii < 4; ii++) {
            int i = ty + ii * 16;
            size_t base = (((size_t)b * PH + h) * PS + st_k[i]) * (size_t)PD;
#pragma unroll
            for (int g = 0; g < 2; g++) {
                float2 a = unpack2(acc[ii][g]);
                *(float2*)&g_o[base + 2 * tx + 32 * g] = a;  // STG.64, coalesced
            }
        }
    }
}

// ---------------------------------------------------------------------------
// Kernel 4: combine hash rounds: w_h = exp(lse_h - logsumexp_h), out = sum w_h o_h.
// grid: PB*(PS/32), 256 threads. 8-lane groups reduce over hashes via shuffles.
// ---------------------------------------------------------------------------
__global__ void __launch_bounds__(256) k_combine(float* __restrict__ out)
{
    __shared__ float sw[32 * 8];
    int b  = blockIdx.x >> 7;
    int t0 = (blockIdx.x & 127) * 32;
    int tid = threadIdx.x;
    int tl = tid >> 3, h = tid & 7;
    int t = t0 + tl;

    float l = g_lse[((size_t)b * PH + h) * PS + t];
    float m = l;
#pragma unroll
    for (int o = 4; o; o >>= 1) m = fmaxf(m, __shfl_xor_sync(0xffffffffu, m, o));
    float s = __expf(l - m);
#pragma unroll
    for (int o = 4; o; o >>= 1) s += __shfl_xor_sync(0xffffffffu, s, o);
    sw[tl * 8 + h] = __expf(l - (m + __logf(s)));
    __syncthreads();

#pragma unroll
    for (int r = 0; r < 8; r++) {
        int idx = tid + r * 256;
        int tl2 = idx >> 6, d = idx & 63;
        int t2 = t0 + tl2;
        float acc = 0.f;
#pragma unroll
        for (int hh = 0; hh < 8; hh++)
            acc += g_o[(((size_t)b * PH + hh) * PS + t2) * (size_t)PD + d] * sw[tl2 * 8 + hh];
        out[((size_t)b * PS + t2) * (size_t)PD + d] = acc;
    }
}

// ---------------------------------------------------------------------------
extern "C" void kernel_launch(void* const* d_in, const int* in_sizes, int n_in,
                              void* d_out, int out_size)
{
    (void)n_in; (void)in_sizes;
    const float* qk  = (const float*)d_in[0];
    const float* v   = (const float*)d_in[1];
    const float* rot = (const float*)d_in[2];
    float* out = (float*)d_out;

    const int n_main = PB * PS * PD;            // 4194304
    const int n_buck = PB * PH * PS;            // 524288
    int write_buckets = (out_size >= n_main + n_buck) ? 1 : 0;

    cudaFuncSetAttribute(k_attn, cudaFuncAttributeMaxDynamicSharedMemorySize,
                         SMEM3_BYTES);

    k_hash<<<PB * (PS / 256), 256>>>(qk, rot, out + n_main, write_buckets);
    k_sort<<<PB * PH, 128>>>();
    k_attn<<<PB * PCHUNKS, 256, SMEM3_BYTES>>>(qk, v);
    k_combine<<<PB * (PS / 32), 256>>>(out);
}

// round 6
// speedup vs baseline: 1.2250x; 1.0807x over previous
#include <cuda_runtime.h>
#include <math.h>

// Problem constants
#define PB 16      // batch
#define PS 4096    // sequence
#define PD 64      // head dim
#define PH 8       // n_hashes
#define PNB 64     // n_buckets
#define PCHUNKS 512 // chunks per batch (PH * PNB), each of 64 tokens

typedef unsigned long long u64;

// ---- packed fp32x2 helpers (Blackwell FFMA2 path) -------------------------
__device__ __forceinline__ u64 pack2(float x, float y) {
    u64 r; asm("mov.b64 %0, {%1, %2};" : "=l"(r) : "f"(x), "f"(y)); return r;
}
__device__ __forceinline__ float2 unpack2(u64 p) {
    float2 v; asm("mov.b64 {%0, %1}, %2;" : "=f"(v.x), "=f"(v.y) : "l"(p)); return v;
}
__device__ __forceinline__ u64 ffma2(u64 a, u64 b, u64 c) {
    asm("fma.rn.f32x2 %0, %1, %2, %0;" : "+l"(c) : "l"(a), "l"(b));
    return c;
}

// ---------------- scratch (device globals; no allocation allowed) ----------
__device__ unsigned char g_bucket[PB * PH * PS];            // 512 KB
__device__ int           g_st[PB * PH * PS];                // 2 MB   sorted pos -> original t
__device__ float         g_lse[PB * PH * PS];               // 2 MB   [b][h][t]
__device__ float         g_o[(size_t)PB * PH * PS * PD];    // 128 MB [b][h][t][d]

// ---------------------------------------------------------------------------
// Kernel 1: hashing. rotated[i] = sum_f qk[b,t,f] * rot[f,h,i]; argmax over
// [rotated, -rotated] with first-occurrence tie-breaking (match jnp.argmax).
// Packed FFMA2 over bucket pairs: 16 packed accumulators cover 32 buckets.
// grid: PB*(PS/256) blocks, 256 threads. Each thread owns one token.
// ---------------------------------------------------------------------------
__global__ void __launch_bounds__(256) k_hash(
    const float* __restrict__ qk, const float* __restrict__ rot,
    float* __restrict__ out_tail, int write_buckets)
{
    __shared__ float rot_s[64 * 32];   // rotations for one hash round: [f][i]
    int b = blockIdx.x >> 4;
    int t = ((blockIdx.x & 15) << 8) + threadIdx.x;

    const float* qr = qk + ((size_t)b * PS + t) * PD;
    float q[64];
#pragma unroll
    for (int f4 = 0; f4 < 16; f4++) {
        float4 v4 = ((const float4*)qr)[f4];
        q[f4 * 4 + 0] = v4.x; q[f4 * 4 + 1] = v4.y;
        q[f4 * 4 + 2] = v4.z; q[f4 * 4 + 3] = v4.w;
    }

    for (int h = 0; h < PH; h++) {
        __syncthreads();
        for (int e = threadIdx.x; e < 2048; e += 256) {
            int f = e >> 5, i = e & 31;
            rot_s[e] = rot[f * 256 + h * 32 + i];  // rot layout [f][h][i] (b bcast)
        }
        __syncthreads();

        u64 acc[16];
#pragma unroll
        for (int p = 0; p < 16; p++) acc[p] = 0ull;   // (0.0f, 0.0f)

        for (int f = 0; f < 64; f++) {
            u64 qb = pack2(q[f], q[f]);
            const ulonglong2* rr = (const ulonglong2*)&rot_s[f * 32]; // LDS.128 bcast
#pragma unroll
            for (int p2 = 0; p2 < 8; p2++) {
                ulonglong2 vv = rr[p2];
                acc[2 * p2 + 0] = ffma2(qb, vv.x, acc[2 * p2 + 0]);
                acc[2 * p2 + 1] = ffma2(qb, vv.y, acc[2 * p2 + 1]);
            }
        }

        float bestp = -1e30f, bestn = -1e30f;
        int ip = 0, inn = 0;
#pragma unroll
        for (int p = 0; p < 16; p++) {
            float2 a = unpack2(acc[p]);
            int i0 = 2 * p, i1 = 2 * p + 1;
            if ( a.x > bestp) { bestp =  a.x; ip  = i0; }
            if (-a.x > bestn) { bestn = -a.x; inn = i0; }
            if ( a.y > bestp) { bestp =  a.y; ip  = i1; }
            if (-a.y > bestn) { bestn = -a.y; inn = i1; }
        }
        int idx = (bestp >= bestn) ? ip : (32 + inn);  // plus-half wins ties
        g_bucket[((size_t)b * PH + h) * PS + t] = (unsigned char)idx;
        if (write_buckets)
            out_tail[((size_t)b * PH + h) * PS + t] = (float)(idx + h * PNB);
    }
}

// ---------------------------------------------------------------------------
// Kernel 2: stable counting sort per (b,h): 4096 tokens into 64 buckets by
// (bucket, t) — exactly jnp.argsort of S*bucket + t. grid: PB*PH, 128 threads.
// ---------------------------------------------------------------------------
__global__ void __launch_bounds__(128) k_sort()
{
    __shared__ unsigned char sb[4096];
    __shared__ int hist[64];
    __shared__ int offs[64];
    int bh = blockIdx.x;
    int tid = threadIdx.x;

    if (tid < 64) hist[tid] = 0;
    const unsigned int* src = (const unsigned int*)(g_bucket + (size_t)bh * PS);
    unsigned int* dstb = (unsigned int*)sb;
    for (int i = tid; i < 1024; i += 128) dstb[i] = src[i];
    __syncthreads();

    for (int t = tid; t < 4096; t += 128) atomicAdd(&hist[sb[t]], 1);
    __syncthreads();

    if (tid == 0) {
        int run = 0;
        for (int k = 0; k < 64; k++) { offs[k] = run; run += hist[k]; }
    }
    __syncthreads();

    if (tid < 64) {
        int k = tid;
        int pos = offs[k];
        int* dst = g_st + (size_t)bh * PS;
        for (int t = 0; t < 4096; t++)
            if (sb[t] == (unsigned char)k) dst[pos++] = t;  // stable: t ascending
    }
}

// ---------------------------------------------------------------------------
// Kernel 3: chunk attention, FFMA2 + register softmax. One CTA per (b,c).
//   Q (64x64, q_s stride 68 for 16B-aligned LDS.128 over kk),
//   K^T (128 j, stride 130), dots/P in registers through softmax, P written
//   once to smem (stride 132, 16B-aligned LDS.128 over j), O = P V with
//   deferred 1/s normalization, scatter by st (fused unsort).
// Thread map: ty=tid>>4 (rows i = ty+16*ii), tx=tid&15 (j/d pairs 2tx+32g).
// 256 threads, dynamic smem 84992 B.
// ---------------------------------------------------------------------------
#define SM_Q   (64 * 68)     // 4352 floats  (row stride 68 -> 272B, 16B-aligned)
#define SM_KV  (64 * 130)    // 8320 floats  (K^T pad 130; reused for V [128][64])
#define SM_DOT (64 * 132)    // 8448 floats  (P stride 132 -> 528B, 16B-aligned)
#define SMEM3_BYTES ((SM_Q + SM_KV + SM_DOT) * 4 + 128 * 4)

__global__ void __launch_bounds__(256) k_attn(
    const float* __restrict__ qk, const float* __restrict__ v)
{
    extern __shared__ float sm[];
    float* q_s  = sm;                     // [i*68 + f]
    float* kv_s = sm + SM_Q;              // K^T: [f*130 + j]; later V: [j*64 + d]
    float* p_s  = sm + SM_Q + SM_KV;      // P: [i*132 + j] (post-softmax only)
    int*   st_k = (int*)(p_s + SM_DOT);   // 128 orig positions (0..63 = Q chunk)

    int tid = threadIdx.x;
    int b = blockIdx.x >> 9;
    int c = blockIdx.x & 511;
    int h  = c >> 6;
    int cp = (c + 511) & 511;
    int hp = cp >> 6;

    if (tid < 64) {
        st_k[tid]      = g_st[((size_t)b * PH + h ) * PS + (c  & 63) * 64 + tid];
        st_k[64 + tid] = g_st[((size_t)b * PH + hp) * PS + (cp & 63) * 64 + tid];
    }
    __syncthreads();

    // ---- load Q (raw) ----
    {
        int i  = tid >> 2;
        int f0 = (tid & 3) * 16;
        const float* row = qk + ((size_t)b * PS + st_k[i]) * PD + f0;
#pragma unroll
        for (int u = 0; u < 4; u++) {
            float4 v4 = ((const float4*)row)[u];
            int f = f0 + u * 4;
            q_s[i * 68 + f + 0] = v4.x; q_s[i * 68 + f + 1] = v4.y;
            q_s[i * 68 + f + 2] = v4.z; q_s[i * 68 + f + 3] = v4.w;
        }
    }
    // ---- load K: row-normalized (clip 1e-12), transposed, stride 130 ----
    if (tid < 128) {
        int j = tid;
        const float* row = qk + ((size_t)b * PS + st_k[j]) * PD;
        float r[64];
        float ss = 0.f;
#pragma unroll
        for (int u = 0; u < 16; u++) {
            float4 v4 = ((const float4*)row)[u];
            r[u * 4 + 0] = v4.x; r[u * 4 + 1] = v4.y;
            r[u * 4 + 2] = v4.z; r[u * 4 + 3] = v4.w;
            ss += v4.x * v4.x + v4.y * v4.y + v4.z * v4.z + v4.w * v4.w;
        }
        float nrm = fmaxf(sqrtf(ss), 1e-12f);
        float inv = 1.0f / nrm;
#pragma unroll
        for (int f = 0; f < 64; f++) kv_s[f * 130 + j] = r[f] * inv;
    }
    __syncthreads();

    int ty = tid >> 4, tx = tid & 15;
    float row_inv[4];   // deferred 1/s per owned row (survives to PV epilogue)

    // ---- dots = Q K^T (FFMA2, kk-unrolled x4, LDS.128 Q) ----
    {
        u64 acc[4][4];
#pragma unroll
        for (int ii = 0; ii < 4; ii++)
#pragma unroll
            for (int g = 0; g < 4; g++) acc[ii][g] = 0ull;

        for (int kk0 = 0; kk0 < 64; kk0 += 4) {
            float qa[4][4];
#pragma unroll
            for (int ii = 0; ii < 4; ii++) {
                float4 q4 = *(const float4*)&q_s[(ty + ii * 16) * 68 + kk0]; // LDS.128
                qa[ii][0] = q4.x; qa[ii][1] = q4.y; qa[ii][2] = q4.z; qa[ii][3] = q4.w;
            }
#pragma unroll
            for (int u = 0; u < 4; u++) {
                int kk = kk0 + u;
                u64 kp[4];
#pragma unroll
                for (int g = 0; g < 4; g++)
                    kp[g] = *(const u64*)&kv_s[kk * 130 + 2 * tx + 32 * g]; // LDS.64
#pragma unroll
                for (int ii = 0; ii < 4; ii++) {
                    u64 qb = pack2(qa[ii][u], qa[ii][u]);
#pragma unroll
                    for (int g = 0; g < 4; g++)
                        acc[ii][g] = ffma2(qb, kp[g], acc[ii][g]);
                }
            }
        }

        // ---- scale + self-mask + register softmax (16-lane shfl rows) ----
        int tj[8];
#pragma unroll
        for (int g = 0; g < 4; g++) {
            tj[2 * g]     = st_k[2 * tx + 32 * g];
            tj[2 * g + 1] = st_k[2 * tx + 32 * g + 1];
        }
#pragma unroll
        for (int ii = 0; ii < 4; ii++) {
            int i = ty + ii * 16;
            int ti = st_k[i];
            float2 p[4];
#pragma unroll
            for (int g = 0; g < 4; g++) {
                p[g] = unpack2(acc[ii][g]);
                p[g].x *= 0.125f; p[g].y *= 0.125f;
                if (ti == tj[2 * g])     p[g].x = -1e5f;
                if (ti == tj[2 * g + 1]) p[g].y = -1e5f;
            }
            // row max across this thread's 8 + 16 lanes
            float m = fmaxf(fmaxf(fmaxf(p[0].x, p[0].y), fmaxf(p[1].x, p[1].y)),
                            fmaxf(fmaxf(p[2].x, p[2].y), fmaxf(p[3].x, p[3].y)));
            m = fmaxf(m, __shfl_xor_sync(0xffffffffu, m, 1));
            m = fmaxf(m, __shfl_xor_sync(0xffffffffu, m, 2));
            m = fmaxf(m, __shfl_xor_sync(0xffffffffu, m, 4));
            m = fmaxf(m, __shfl_xor_sync(0xffffffffu, m, 8));
            float s = 0.f;
#pragma unroll
            for (int g = 0; g < 4; g++) {
                p[g].x = __expf(p[g].x - m);
                p[g].y = __expf(p[g].y - m);
                s += p[g].x + p[g].y;
            }
            s += __shfl_xor_sync(0xffffffffu, s, 1);
            s += __shfl_xor_sync(0xffffffffu, s, 2);
            s += __shfl_xor_sync(0xffffffffu, s, 4);
            s += __shfl_xor_sync(0xffffffffu, s, 8);
            row_inv[ii] = 1.0f / s;     // normalization deferred to O epilogue
            // write unnormalized P once
#pragma unroll
            for (int g = 0; g < 4; g++)
                *(float2*)&p_s[i * 132 + 2 * tx + 32 * g] = p[g];
            if (tx == 0)
                g_lse[((size_t)b * PH + h) * PS + ti] = m + __logf(s);
        }
    }
    __syncthreads();   // all K^T reads done -> safe to overwrite kv_s with V

    // ---- load V into kv_s ----
    {
        int j  = tid >> 1;
        int d0 = (tid & 1) * 32;
        const float* row = v + ((size_t)b * PS + st_k[j]) * PD + d0;
        float* dv = kv_s + j * 64 + d0;
#pragma unroll
        for (int u = 0; u < 8; u++)
            ((float4*)dv)[u] = ((const float4*)row)[u];
    }
    __syncthreads();

    // ---- O = P V (FFMA2, j-unrolled x4, LDS.128 P), scale by 1/s, scatter --
    {
        u64 oacc[4][2];
#pragma unroll
        for (int ii = 0; ii < 4; ii++) { oacc[ii][0] = 0ull; oacc[ii][1] = 0ull; }

        for (int j0 = 0; j0 < 128; j0 += 4) {
            float pa[4][4];
#pragma unroll
            for (int ii = 0; ii < 4; ii++) {
                float4 p4 = *(const float4*)&p_s[(ty + ii * 16) * 132 + j0]; // LDS.128
                pa[ii][0] = p4.x; pa[ii][1] = p4.y; pa[ii][2] = p4.z; pa[ii][3] = p4.w;
            }
#pragma unroll
            for (int u = 0; u < 4; u++) {
                int j = j0 + u;
                u64 vp0 = *(const u64*)&kv_s[j * 64 + 2 * tx];       // LDS.64
                u64 vp1 = *(const u64*)&kv_s[j * 64 + 2 * tx + 32];
#pragma unroll
                for (int ii = 0; ii < 4; ii++) {
                    u64 pb = pack2(pa[ii][u], pa[ii][u]);
                    oacc[ii][0] = ffma2(pb, vp0, oacc[ii][0]);
                    oacc[ii][1] = ffma2(pb, vp1, oacc[ii][1]);
                }
            }
        }
#pragma unroll
        for (int ii = 0; ii < 4; ii++) {
            int i = ty + ii * 16;
            float inv = row_inv[ii];
            size_t base = (((size_t)b * PH + h) * PS + st_k[i]) * (size_t)PD;
#pragma unroll
            for (int g = 0; g < 2; g++) {
                float2 a = unpack2(oacc[ii][g]);
                a.x *= inv; a.y *= inv;
                *(float2*)&g_o[base + 2 * tx + 32 * g] = a;  // STG.64, coalesced
            }
        }
    }
}

// ---------------------------------------------------------------------------
// Kernel 4: combine hash rounds: w_h = exp(lse_h - logsumexp_h), out = sum w_h o_h.
// grid: PB*(PS/32), 256 threads. 8-lane groups reduce over hashes via shuffles.
// ---------------------------------------------------------------------------
__global__ void __launch_bounds__(256) k_combine(float* __restrict__ out)
{
    __shared__ float sw[32 * 8];
    int b  = blockIdx.x >> 7;
    int t0 = (blockIdx.x & 127) * 32;
    int tid = threadIdx.x;
    int tl = tid >> 3, h = tid & 7;
    int t = t0 + tl;

    float l = g_lse[((size_t)b * PH + h) * PS + t];
    float m = l;
#pragma unroll
    for (int o = 4; o; o >>= 1) m = fmaxf(m, __shfl_xor_sync(0xffffffffu, m, o));
    float s = __expf(l - m);
#pragma unroll
    for (int o = 4; o; o >>= 1) s += __shfl_xor_sync(0xffffffffu, s, o);
    sw[tl * 8 + h] = __expf(l - (m + __logf(s)));
    __syncthreads();

#pragma unroll
    for (int r = 0; r < 8; r++) {
        int idx = tid + r * 256;
        int tl2 = idx >> 6, d = idx & 63;
        int t2 = t0 + tl2;
        float acc = 0.f;
#pragma unroll
        for (int hh = 0; hh < 8; hh++)
            acc += g_o[(((size_t)b * PH + hh) * PS + t2) * (size_t)PD + d] * sw[tl2 * 8 + hh];
        out[((size_t)b * PS + t2) * (size_t)PD + d] = acc;
    }
}

// ---------------------------------------------------------------------------
extern "C" void kernel_launch(void* const* d_in, const int* in_sizes, int n_in,
                              void* d_out, int out_size)
{
    (void)n_in; (void)in_sizes;
    const float* qk  = (const float*)d_in[0];
    const float* v   = (const float*)d_in[1];
    const float* rot = (const float*)d_in[2];
    float* out = (float*)d_out;

    const int n_main = PB * PS * PD;            // 4194304
    const int n_buck = PB * PH * PS;            // 524288
    int write_buckets = (out_size >= n_main + n_buck) ? 1 : 0;

    cudaFuncSetAttribute(k_attn, cudaFuncAttributeMaxDynamicSharedMemorySize,
                         SMEM3_BYTES);

    k_hash<<<PB * (PS / 256), 256>>>(qk, rot, out + n_main, write_buckets);
    k_sort<<<PB * PH, 128>>>();
    k_attn<<<PB * PCHUNKS, 256, SMEM3_BYTES>>>(qk, v);
    k_combine<<<PB * (PS / 32), 256>>>(out);
}